// round 13
// baseline (speedup 1.0000x reference)
#include <cuda_runtime.h>
#include <cuda_fp16.h>
#include <cstdint>

constexpr int M = 1024;
constexpr int N = 32768;
constexpr int K = 512;
constexpr float MARGIN = 0.3f;

constexpr int BM = 128, BK = 64;
constexpr int NCH = K / BK;              // 8
constexpr int ROWB = 128;                // 64 f16 = 128B row, SW128

// Mixed-tile partition: per row-block, 111 x BN256 + 34 x BN128 = 32768 cols.
constexpr int NBX_BIG = 111;
constexpr int NBX_SML = 34;
constexpr int BIG_CTAS = NBX_BIG * (M / BM);        // 888 = 3 x 296 slots
constexpr int TOT_CTAS = BIG_CTAS + NBX_SML * (M / BM);   // 1160
constexpr int COL_SML0 = NBX_BIG * 256;             // 28416

// dynamic smem layout sized for the BIG tile (small path uses a prefix)
constexpr uint32_t OFF_LAB = 0;                          // up to 256 ints
constexpr uint32_t OFF_A   = 1024;
constexpr uint32_t A_STAGE = BM * ROWB;                  // 16384
constexpr uint32_t OFF_B   = OFF_A + 2 * A_STAGE;        // 33792
constexpr uint32_t B_STAGE = 256 * ROWB;                 // 32768
constexpr uint32_t SMEM_TOTAL = OFF_B + 2 * B_STAGE;     // 99328 (2 CTAs/SM)

__device__ unsigned g_posU[M];
__device__ unsigned g_negU[M];
__device__ unsigned g_ctr;
__device__ __half g_Ah[M * K];
__device__ __half g_Bh[(size_t)N * K];

__device__ __forceinline__ float f_inf()  { return __int_as_float(0x7f800000); }
__device__ __forceinline__ float f_ninf() { return __int_as_float(0xff800000); }

__device__ __forceinline__ unsigned encOrd(float f) {
    unsigned b = __float_as_uint(f);
    return (b & 0x80000000u) ? ~b : (b | 0x80000000u);
}
__device__ __forceinline__ float decOrd(unsigned u) {
    return (u & 0x80000000u) ? __uint_as_float(u ^ 0x80000000u)
                             : __uint_as_float(~u);
}

__device__ __forceinline__ uint32_t swz(uint32_t b) { return b ^ ((b >> 3) & 0x70); }

__device__ __forceinline__ uint32_t smem_u32(const void* p) {
    uint32_t a;
    asm("{ .reg .u64 t; cvta.to.shared.u64 t, %1; cvt.u32.u64 %0, t; }" : "=r"(a) : "l"(p));
    return a;
}
__device__ __forceinline__ void ldsm_x4(uint32_t* r, uint32_t addr) {
    asm volatile("ldmatrix.sync.aligned.m8n8.x4.shared.b16 {%0,%1,%2,%3}, [%4];"
                 : "=r"(r[0]), "=r"(r[1]), "=r"(r[2]), "=r"(r[3]) : "r"(addr));
}
__device__ __forceinline__ void mma_f16(uint32_t* d, const uint32_t* a, const uint32_t* b) {
    asm volatile(
        "mma.sync.aligned.m16n8k16.row.col.f16.f16.f16.f16 "
        "{%0,%1}, {%2,%3,%4,%5}, {%6,%7}, {%0,%1};"
        : "+r"(d[0]), "+r"(d[1])
        : "r"(a[0]), "r"(a[1]), "r"(a[2]), "r"(a[3]), "r"(b[0]), "r"(b[1]));
}
__device__ __forceinline__ void cp_async16(uint32_t dst, const void* src) {
    asm volatile("cp.async.cg.shared.global [%0], [%1], 16;" :: "r"(dst), "l"(src));
}
__device__ __forceinline__ void cp_commit() {
    asm volatile("cp.async.commit_group;" ::: "memory");
}
template <int NG> __device__ __forceinline__ void cp_wait() {
    asm volatile("cp.async.wait_group %0;" :: "n"(NG) : "memory");
}

// fp32 -> f16 scratch (streaming), plus min/max array init.
__global__ void tl_quant(const float* __restrict__ A, const float* __restrict__ B) {
    const int gid = blockIdx.x * blockDim.x + threadIdx.x;
    const int nth = gridDim.x * blockDim.x;
    if (gid < M) { g_posU[gid] = 0xFFFFFFFFu; g_negU[gid] = 0u; }

    auto pack8 = [](float4 a, float4 b) {
        __half2 h0 = __floats2half2_rn(a.x, a.y);
        __half2 h1 = __floats2half2_rn(a.z, a.w);
        __half2 h2 = __floats2half2_rn(b.x, b.y);
        __half2 h3 = __floats2half2_rn(b.z, b.w);
        return make_uint4(*(uint32_t*)&h0, *(uint32_t*)&h1,
                          *(uint32_t*)&h2, *(uint32_t*)&h3);
    };

    for (int i = gid; i < M * K / 8; i += nth) {
        const float4* src = reinterpret_cast<const float4*>(A) + 2 * (size_t)i;
        float4 v0 = __ldcs(src), v1 = __ldcs(src + 1);
        __stcs(reinterpret_cast<uint4*>(g_Ah) + i, pack8(v0, v1));
    }
#pragma unroll 4
    for (size_t i = gid; i < (size_t)N * K / 8; i += nth) {
        const float4* src = reinterpret_cast<const float4*>(B) + 2 * i;
        float4 v0 = __ldcs(src), v1 = __ldcs(src + 1);
        __stcs(reinterpret_cast<uint4*>(g_Bh) + i, pack8(v0, v1));
    }
}

// One tile's full work. NI = BN/32: 8 -> BN=256 (warp tile 64x64),
//                                  4 -> BN=128 (warp tile 64x32).
template <int NI>
__device__ __forceinline__ void do_tile(
    const int* __restrict__ targets, const int* __restrict__ idxv,
    const int* __restrict__ labels,
    int rowBase, int colBase,
    uint32_t sb, int tid, int lane, int wid,
    int* sLab, int* sT, int* sI, unsigned* sPosU, unsigned* sNegU)
{
    constexpr int BN = NI * 32;
    constexpr int NG = NI / 2;           // b-fragment ldsm_x4 groups

    const uint32_t sA = sb + OFF_A;
    const uint32_t sB = sb + OFF_B;

    // 8 warps: 2 (m) x 4 (n); warp tile 64 x (BN/4)
    const int warp_m = (wid >> 2) * 64;
    const int warp_n = (wid & 3) * (BN / 4);

    for (int i = tid; i < BN; i += 256) sLab[i] = labels[colBase + i];
    if (tid < BM) {
        sT[tid] = targets[rowBase + tid];
        sI[tid] = idxv[rowBase + tid];
        sPosU[tid] = 0xFFFFFFFFu;
        sNegU[tid] = 0u;
    }

    auto load_stage = [&](int st, int c) {
        const int kb = c * BK;
        const uint32_t dA = sA + st * A_STAGE;
        const uint32_t dB = sB + st * B_STAGE;
#pragma unroll
        for (int i = 0; i < 4; ++i) {
            const int v = tid + i * 256;
            const int r = v >> 3, q = v & 7;
            cp_async16(dA + swz((uint32_t)(r * ROWB + q * 16)),
                       g_Ah + (size_t)(rowBase + r) * K + kb + q * 8);
        }
#pragma unroll
        for (int i = 0; i < NI; ++i) {
            const int v = tid + i * 256;
            const int r = v >> 3, q = v & 7;
            cp_async16(dB + swz((uint32_t)(r * ROWB + q * 16)),
                       g_Bh + (size_t)(colBase + r) * K + kb + q * 8);
        }
        cp_commit();
    };

    // Hoisted pre-swizzled ldmatrix bases; swz(base + ks*32) == swz(base) ^ (ks<<5)
    uint32_t aB[4], bB[NG];
#pragma unroll
    for (int mi = 0; mi < 4; ++mi)
        aB[mi] = swz((uint32_t)(warp_m + (lane & 15) + mi * 16) * ROWB
                     + (lane >> 4) * 16);
#pragma unroll
    for (int g = 0; g < NG; ++g)
        bB[g] = swz((uint32_t)(warp_n + (lane & 7) + ((lane >> 4) & 1) * 8 + g * 16) * ROWB
                    + ((lane >> 3) & 1) * 16);

    uint32_t acc[4][NI][2] = {};

    load_stage(0, 0);
    load_stage(1, 1);

#pragma unroll 1
    for (int c = 0; c < NCH; ++c) {
        if (c + 1 < NCH) cp_wait<1>(); else cp_wait<0>();
        __syncthreads();

        const uint32_t stA = sA + (c & 1) * A_STAGE;
        const uint32_t stB = sB + (c & 1) * B_STAGE;
#pragma unroll
        for (int ks = 0; ks < 4; ++ks) {
            const uint32_t kx = (uint32_t)ks << 5;
            uint32_t af[4][4], bfr[NG][4];
#pragma unroll
            for (int mi = 0; mi < 4; ++mi)
                ldsm_x4(af[mi], stA + (aB[mi] ^ kx));
#pragma unroll
            for (int g = 0; g < NG; ++g)
                ldsm_x4(bfr[g], stB + (bB[g] ^ kx));
#pragma unroll
            for (int mi = 0; mi < 4; ++mi)
#pragma unroll
                for (int ni = 0; ni < NI; ++ni)
                    mma_f16(acc[mi][ni], af[mi], &bfr[ni >> 1][(ni & 1) * 2]);
        }

        if (c + 2 < NCH) {
            __syncthreads();
            load_stage(c & 1, c + 2);
        }
    }
    __syncthreads();

    const int lq = lane >> 2;
    const int lr = (lane & 3) * 2;
#pragma unroll
    for (int mi = 0; mi < 4; ++mi) {
#pragma unroll
        for (int h = 0; h < 2; ++h) {
            const int rloc = warp_m + mi * 16 + h * 8 + lq;
            const int tg = sT[rloc];
            const int ix = sI[rloc];
            float pmin = f_inf(), nmax = f_ninf();
#pragma unroll
            for (int ni = 0; ni < NI; ++ni) {
                const float2 f2 = __half22float2(
                    *reinterpret_cast<const __half2*>(&acc[mi][ni][h]));
#pragma unroll
                for (int j = 0; j < 2; ++j) {
                    const int cloc = warp_n + ni * 8 + lr + j;
                    const float v = (j == 0) ? f2.x : f2.y;
                    if (sLab[cloc] == tg) {
                        if (colBase + cloc != ix) pmin = fminf(pmin, v);
                    } else {
                        nmax = fmaxf(nmax, v);
                    }
                }
            }
            if (pmin <  f_inf())  atomicMin(&sPosU[rloc], encOrd(pmin));
            if (nmax > f_ninf())  atomicMax(&sNegU[rloc], encOrd(nmax));
        }
    }
    __syncthreads();

    if (tid < BM) {
        const unsigned p = sPosU[tid], q = sNegU[tid];
        if (p != 0xFFFFFFFFu) atomicMin(&g_posU[rowBase + tid], p);
        if (q != 0u)          atomicMax(&g_negU[rowBase + tid], q);
    }
}

__global__ __launch_bounds__(256, 2)
void tl_gemm(const int* __restrict__ targets, const int* __restrict__ idxv,
             const int* __restrict__ labels, float* __restrict__ out)
{
    extern __shared__ __align__(1024) char smem[];
    __shared__ int      sT[BM];
    __shared__ int      sI[BM];
    __shared__ unsigned sPosU[BM];
    __shared__ unsigned sNegU[BM];
    __shared__ float    sRed[8];
    __shared__ unsigned sIsLast;

    const uint32_t sb = smem_u32(smem);
    int* sLab = (int*)(smem + OFF_LAB);

    const int tid  = threadIdx.x;
    const int lane = tid & 31;
    const int wid  = tid >> 5;
    const int bid  = blockIdx.x;

    if (bid < BIG_CTAS) {
        const int rowBase = (bid / NBX_BIG) * BM;
        const int colBase = (bid % NBX_BIG) * 256;
        do_tile<8>(targets, idxv, labels, rowBase, colBase,
                   sb, tid, lane, wid, sLab, sT, sI, sPosU, sNegU);
    } else {
        const int j = bid - BIG_CTAS;
        const int rowBase = (j / NBX_SML) * BM;
        const int colBase = COL_SML0 + (j % NBX_SML) * 128;
        do_tile<4>(targets, idxv, labels, rowBase, colBase,
                   sb, tid, lane, wid, sLab, sT, sI, sPosU, sNegU);
    }

    // ---- fused finale ----
    __threadfence();
    if (tid == 0) {
        sIsLast = (atomicAdd(&g_ctr, 1u) == (unsigned)gridDim.x - 1u);
    }
    __syncthreads();
    if (!sIsLast) return;

    __threadfence();
    float l = 0.f;
#pragma unroll
    for (int r = 0; r < 4; ++r) {
        const int row = tid + r * 256;
        const float pos = decOrd(__ldcg(&g_posU[row]));
        const float neg = decOrd(__ldcg(&g_negU[row]));
        l += fmaxf(neg - pos + MARGIN, 0.0f);
    }
#pragma unroll
    for (int o = 16; o > 0; o >>= 1) l += __shfl_xor_sync(0xffffffffu, l, o);
    if (lane == 0) sRed[wid] = l;
    __syncthreads();
    if (tid < 8) {
        float s = sRed[tid];
#pragma unroll
        for (int o = 4; o > 0; o >>= 1) s += __shfl_xor_sync(0xffu, s, o);
        if (tid == 0) {
            out[0] = s * (1.0f / (float)M);
            g_ctr = 0;
        }
    }
}

extern "C" void kernel_launch(void* const* d_in, const int* in_sizes, int n_in,
                              void* d_out, int out_size) {
    const float* A       = (const float*)d_in[0];
    const float* B       = (const float*)d_in[1];
    const int*   targets = (const int*)  d_in[2];
    const int*   idxv    = (const int*)  d_in[3];
    const int*   labels  = (const int*)  d_in[4];
    float*       out     = (float*)d_out;

    static bool attrSet = false;
    if (!attrSet) {
        cudaFuncSetAttribute(tl_gemm, cudaFuncAttributeMaxDynamicSharedMemorySize,
                             SMEM_TOTAL);
        attrSet = true;
    }

    tl_quant<<<1024, 256>>>(A, B);
    tl_gemm<<<TOT_CTAS, 256, SMEM_TOTAL>>>(targets, idxv, labels, out);
}

// round 14
// speedup vs baseline: 1.0207x; 1.0207x over previous
#include <cuda_runtime.h>
#include <cuda_fp16.h>
#include <cstdint>

constexpr int M = 1024;
constexpr int N = 32768;
constexpr int K = 512;
constexpr float MARGIN = 0.3f;

constexpr int BM = 128, BN = 256, BK = 64;
constexpr int NCH = K / BK;              // 8
constexpr int ROWB = 128;                // 64 f16 = 128B row, SW128 swizzle

// dynamic smem layout (double buffered, SW128)
constexpr uint32_t OFF_LAB = 0;                          // 256 ints = 1KB
constexpr uint32_t OFF_A   = 1024;
constexpr uint32_t A_STAGE = BM * ROWB;                  // 16384
constexpr uint32_t OFF_B   = OFF_A + 2 * A_STAGE;        // 33792
constexpr uint32_t B_STAGE = BN * ROWB;                  // 32768
constexpr uint32_t SMEM_TOTAL = OFF_B + 2 * B_STAGE;     // 99328 (x2 CTAs/SM)

__device__ unsigned g_posU[M];
__device__ unsigned g_negU[M];
__device__ unsigned g_ctr;
__device__ __half g_Ah[M * K];
__device__ __half g_Bh[(size_t)N * K];

__device__ __forceinline__ float f_inf()  { return __int_as_float(0x7f800000); }
__device__ __forceinline__ float f_ninf() { return __int_as_float(0xff800000); }

__device__ __forceinline__ unsigned encOrd(float f) {
    unsigned b = __float_as_uint(f);
    return (b & 0x80000000u) ? ~b : (b | 0x80000000u);
}
__device__ __forceinline__ float decOrd(unsigned u) {
    return (u & 0x80000000u) ? __uint_as_float(u ^ 0x80000000u)
                             : __uint_as_float(~u);
}

__device__ __forceinline__ uint32_t swz(uint32_t b) { return b ^ ((b >> 3) & 0x70); }

__device__ __forceinline__ uint32_t smem_u32(const void* p) {
    uint32_t a;
    asm("{ .reg .u64 t; cvta.to.shared.u64 t, %1; cvt.u32.u64 %0, t; }" : "=r"(a) : "l"(p));
    return a;
}
__device__ __forceinline__ void ldsm_x4(uint32_t* r, uint32_t addr) {
    asm volatile("ldmatrix.sync.aligned.m8n8.x4.shared.b16 {%0,%1,%2,%3}, [%4];"
                 : "=r"(r[0]), "=r"(r[1]), "=r"(r[2]), "=r"(r[3]) : "r"(addr));
}
__device__ __forceinline__ void mma_f16(uint32_t* d, const uint32_t* a, const uint32_t* b) {
    asm volatile(
        "mma.sync.aligned.m16n8k16.row.col.f16.f16.f16.f16 "
        "{%0,%1}, {%2,%3,%4,%5}, {%6,%7}, {%0,%1};"
        : "+r"(d[0]), "+r"(d[1])
        : "r"(a[0]), "r"(a[1]), "r"(a[2]), "r"(a[3]), "r"(b[0]), "r"(b[1]));
}
__device__ __forceinline__ void cp_async16(uint32_t dst, const void* src) {
    asm volatile("cp.async.cg.shared.global [%0], [%1], 16;" :: "r"(dst), "l"(src));
}
__device__ __forceinline__ void cp_commit() {
    asm volatile("cp.async.commit_group;" ::: "memory");
}
template <int NG> __device__ __forceinline__ void cp_wait() {
    asm volatile("cp.async.wait_group %0;" :: "n"(NG) : "memory");
}

// fp32 -> f16 scratch (streaming), plus min/max array init.
__global__ void tl_quant(const float* __restrict__ A, const float* __restrict__ B) {
    const int gid = blockIdx.x * blockDim.x + threadIdx.x;
    const int nth = gridDim.x * blockDim.x;
    if (gid < M) { g_posU[gid] = 0xFFFFFFFFu; g_negU[gid] = 0u; }

    auto pack8 = [](float4 a, float4 b) {
        __half2 h0 = __floats2half2_rn(a.x, a.y);
        __half2 h1 = __floats2half2_rn(a.z, a.w);
        __half2 h2 = __floats2half2_rn(b.x, b.y);
        __half2 h3 = __floats2half2_rn(b.z, b.w);
        return make_uint4(*(uint32_t*)&h0, *(uint32_t*)&h1,
                          *(uint32_t*)&h2, *(uint32_t*)&h3);
    };

    for (int i = gid; i < M * K / 8; i += nth) {
        const float4* src = reinterpret_cast<const float4*>(A) + 2 * (size_t)i;
        float4 v0 = __ldcs(src), v1 = __ldcs(src + 1);
        __stcs(reinterpret_cast<uint4*>(g_Ah) + i, pack8(v0, v1));
    }
#pragma unroll 4
    for (size_t i = gid; i < (size_t)N * K / 8; i += nth) {
        const float4* src = reinterpret_cast<const float4*>(B) + 2 * i;
        float4 v0 = __ldcs(src), v1 = __ldcs(src + 1);
        __stcs(reinterpret_cast<uint4*>(g_Bh) + i, pack8(v0, v1));
    }
}

__global__ __launch_bounds__(256, 2)
void tl_gemm(const int* __restrict__ targets, const int* __restrict__ idxv,
             const int* __restrict__ labels, float* __restrict__ out)
{
    extern __shared__ __align__(1024) char smem[];
    __shared__ int      sT[BM];
    __shared__ int      sI[BM];
    __shared__ unsigned sPosU[BM];
    __shared__ unsigned sNegU[BM];
    __shared__ float    sRed[8];
    __shared__ unsigned sIsLast;

    const uint32_t sb = smem_u32(smem);
    const uint32_t sA = sb + OFF_A;
    const uint32_t sB = sb + OFF_B;
    int* sLab = (int*)(smem + OFF_LAB);

    const int tid  = threadIdx.x;
    const int lane = tid & 31;
    const int wid  = tid >> 5;
    const int rowBase = blockIdx.y * BM;
    const int colBase = blockIdx.x * BN;

    // 8 warps: 2 (m) x 4 (n); warp tile 64 x 64
    const int warp_m = (wid >> 2) * 64;
    const int warp_n = (wid & 3) * 64;

    for (int i = tid; i < BN; i += 256) sLab[i] = labels[colBase + i];
    if (tid < BM) {
        sT[tid] = targets[rowBase + tid];
        sI[tid] = idxv[rowBase + tid];
        sPosU[tid] = 0xFFFFFFFFu;
        sNegU[tid] = 0u;
    }

    auto load_stage = [&](int st, int c) {
        const int kb = c * BK;
        const uint32_t dA = sA + st * A_STAGE;
        const uint32_t dB = sB + st * B_STAGE;
#pragma unroll
        for (int i = 0; i < 4; ++i) {
            const int v = tid + i * 256;
            const int r = v >> 3, q = v & 7;
            cp_async16(dA + swz((uint32_t)(r * ROWB + q * 16)),
                       g_Ah + (size_t)(rowBase + r) * K + kb + q * 8);
        }
#pragma unroll
        for (int i = 0; i < 8; ++i) {
            const int v = tid + i * 256;
            const int r = v >> 3, q = v & 7;
            cp_async16(dB + swz((uint32_t)(r * ROWB + q * 16)),
                       g_Bh + (size_t)(colBase + r) * K + kb + q * 8);
        }
        cp_commit();
    };

    // Hoisted, pre-swizzled ldmatrix base addresses.
    // Identity: swz(base + ks*32) == swz(base) ^ (ks<<5)
    uint32_t aB[4], bB[4];
#pragma unroll
    for (int mi = 0; mi < 4; ++mi)
        aB[mi] = swz((uint32_t)(warp_m + (lane & 15) + mi * 16) * ROWB
                     + (lane >> 4) * 16);
#pragma unroll
    for (int g = 0; g < 4; ++g)
        bB[g] = swz((uint32_t)(warp_n + (lane & 7) + ((lane >> 4) & 1) * 8 + g * 16) * ROWB
                    + ((lane >> 3) & 1) * 16);

    uint32_t acc[4][8][2] = {};   // f16x2 accumulators

    load_stage(0, 0);             // prologue: only chunk 0

#pragma unroll 1
    for (int c = 0; c < NCH; ++c) {
        // One barrier per chunk: wait (this thread's group done) -> sync
        // (cross-thread visibility of buf c, AND all warps finished reading
        // buf (c+1)&1 during chunk c-1) -> refill it -> compute chunk c.
        cp_wait<0>();
        __syncthreads();
        if (c + 1 < NCH) load_stage((c + 1) & 1, c + 1);

        const uint32_t stA = sA + (c & 1) * A_STAGE;
        const uint32_t stB = sB + (c & 1) * B_STAGE;
#pragma unroll
        for (int ks = 0; ks < 4; ++ks) {
            const uint32_t kx = (uint32_t)ks << 5;
            uint32_t af[4][4], bfr[4][4];
#pragma unroll
            for (int mi = 0; mi < 4; ++mi)
                ldsm_x4(af[mi], stA + (aB[mi] ^ kx));
#pragma unroll
            for (int g = 0; g < 4; ++g)
                ldsm_x4(bfr[g], stB + (bB[g] ^ kx));
#pragma unroll
            for (int mi = 0; mi < 4; ++mi)
#pragma unroll
                for (int ni = 0; ni < 8; ++ni)
                    mma_f16(acc[mi][ni], af[mi], &bfr[ni >> 1][(ni & 1) * 2]);
        }
    }
    __syncthreads();

    // Epilogue: unpack f16 acc, masked min/max with ordered-uint atomics.
    const int lq = lane >> 2;
    const int lr = (lane & 3) * 2;
#pragma unroll
    for (int mi = 0; mi < 4; ++mi) {
#pragma unroll
        for (int h = 0; h < 2; ++h) {
            const int rloc = warp_m + mi * 16 + h * 8 + lq;
            const int tg = sT[rloc];
            const int ix = sI[rloc];
            float pmin = f_inf(), nmax = f_ninf();
#pragma unroll
            for (int ni = 0; ni < 8; ++ni) {
                const float2 f2 = __half22float2(
                    *reinterpret_cast<const __half2*>(&acc[mi][ni][h]));
#pragma unroll
                for (int j = 0; j < 2; ++j) {
                    const int cloc = warp_n + ni * 8 + lr + j;
                    const float v = (j == 0) ? f2.x : f2.y;
                    if (sLab[cloc] == tg) {
                        if (colBase + cloc != ix) pmin = fminf(pmin, v);
                    } else {
                        nmax = fmaxf(nmax, v);
                    }
                }
            }
            if (pmin <  f_inf())  atomicMin(&sPosU[rloc], encOrd(pmin));
            if (nmax > f_ninf())  atomicMax(&sNegU[rloc], encOrd(nmax));
        }
    }
    __syncthreads();

    if (tid < BM) {
        const unsigned p = sPosU[tid], q = sNegU[tid];
        if (p != 0xFFFFFFFFu) atomicMin(&g_posU[rowBase + tid], p);
        if (q != 0u)          atomicMax(&g_negU[rowBase + tid], q);
    }

    // ---- fused finale ----
    __threadfence();
    if (tid == 0) {
        const unsigned total = gridDim.x * gridDim.y;
        sIsLast = (atomicAdd(&g_ctr, 1u) == total - 1u);
    }
    __syncthreads();
    if (!sIsLast) return;

    __threadfence();
    float l = 0.f;
#pragma unroll
    for (int r = 0; r < 4; ++r) {
        const int row = tid + r * 256;
        const float pos = decOrd(__ldcg(&g_posU[row]));
        const float neg = decOrd(__ldcg(&g_negU[row]));
        l += fmaxf(neg - pos + MARGIN, 0.0f);
    }
#pragma unroll
    for (int o = 16; o > 0; o >>= 1) l += __shfl_xor_sync(0xffffffffu, l, o);
    if (lane == 0) sRed[wid] = l;
    __syncthreads();
    if (tid < 8) {
        float s = sRed[tid];
#pragma unroll
        for (int o = 4; o > 0; o >>= 1) s += __shfl_xor_sync(0xffu, s, o);
        if (tid == 0) {
            out[0] = s * (1.0f / (float)M);
            g_ctr = 0;
        }
    }
}

extern "C" void kernel_launch(void* const* d_in, const int* in_sizes, int n_in,
                              void* d_out, int out_size) {
    const float* A       = (const float*)d_in[0];
    const float* B       = (const float*)d_in[1];
    const int*   targets = (const int*)  d_in[2];
    const int*   idxv    = (const int*)  d_in[3];
    const int*   labels  = (const int*)  d_in[4];
    float*       out     = (float*)d_out;

    static bool attrSet = false;
    if (!attrSet) {
        cudaFuncSetAttribute(tl_gemm, cudaFuncAttributeMaxDynamicSharedMemorySize,
                             SMEM_TOTAL);
        attrSet = true;
    }

    tl_quant<<<1024, 256>>>(A, B);
    dim3 grid(N / BN, M / BM);   // 128 x 8 = 1024 CTAs
    tl_gemm<<<grid, 256, SMEM_TOTAL>>>(targets, idxv, labels, out);
}